// round 7
// baseline (speedup 1.0000x reference)
#include <cuda_runtime.h>
#include <cuda_fp16.h>
#include <cstdint>

#define MAXN 8192
#define HD 64
#define SLOTS 32
#define EMB_MAX (50000 * HD)
#define BLKS 296
#define PROD_W 6
#define CONS_W 2
#define NPROD (BLKS * PROD_W)   // 1776
#define NCONS (BLKS * CONS_W)   // 592
#define GCH 128

// ---------------- static device scratch ----------------
__device__ __half g_embh[EMB_MAX];
__device__ float g_az[MAXN * HD];
__device__ float g_ar[MAXN * HD];
__device__ float g_ah[MAXN * HD];
__device__ float g_h[MAXN * HD];
__device__ int g_cnt[MAXN];
__device__ int g_buck[MAXN * SLOTS];
__device__ int g_wr[MAXN];
__device__ volatile int g_ready[MAXN];    // h ready
__device__ volatile int g_aready[MAXN];   // a ready
__device__ unsigned g_max[HD];
__device__ unsigned g_done;

// ---------------- prep: fp16 embedding conversion + state reset ----------------
__global__ void prep_kernel(const float* __restrict__ emb, const int* __restrict__ tree,
                            int n_steps, int emb_total) {
    int t = blockIdx.x * blockDim.x + threadIdx.x;
    int e = t * 8;
    if (e + 7 < emb_total) {
        float4 f0 = *reinterpret_cast<const float4*>(emb + e);
        float4 f1 = *reinterpret_cast<const float4*>(emb + e + 4);
        *reinterpret_cast<__half2*>(g_embh + e)     = __floats2half2_rn(f0.x, f0.y);
        *reinterpret_cast<__half2*>(g_embh + e + 2) = __floats2half2_rn(f0.z, f0.w);
        *reinterpret_cast<__half2*>(g_embh + e + 4) = __floats2half2_rn(f1.x, f1.y);
        *reinterpret_cast<__half2*>(g_embh + e + 6) = __floats2half2_rn(f1.z, f1.w);
    }
    if (t < n_steps) {
        g_wr[t] = tree[2 * t + 1];
        g_ready[t] = 0;
        g_aready[t] = 0;
    }
    if (t < MAXN) g_cnt[t] = 0;
    if (t < HD) g_max[t] = 0u;
    if (t == 0) g_done = 0u;
}

// ---------------- bucket fill: writes per node ----------------
__global__ void fill_kernel(const int* __restrict__ tree, int n_steps) {
    int i = blockIdx.x * blockDim.x + threadIdx.x;
    if (i >= n_steps) return;
    int v = tree[2 * i + 1];
    int s = atomicAdd(&g_cnt[v], 1);
    if (s < SLOTS) g_buck[v * SLOTS + s] = i;
}

// ---------------- gather one 128-row chunk, index-staged ----------------
__device__ __forceinline__ void gather_chunk(const float* __restrict__ xwr,
                                             const int* __restrict__ xir,
                                             int r0, int rl, int rg, float acc[8]) {
#pragma unroll
    for (int half = 0; half < 2; half++) {
        int hb = r0 + half * 64 + 4 * rg;
        float4 w[4];
        int4 ix[4];
#pragma unroll
        for (int g = 0; g < 4; g++) {
            w[g]  = __ldg(reinterpret_cast<const float4*>(xwr + hb + 16 * g));
            ix[g] = __ldg(reinterpret_cast<const int4*>(xir + hb + 16 * g));
        }
#pragma unroll
        for (int g = 0; g < 4; g++) {
            uint4 u0 = __ldg(reinterpret_cast<const uint4*>(g_embh + (size_t)ix[g].x * HD + rl * 8));
            uint4 u1 = __ldg(reinterpret_cast<const uint4*>(g_embh + (size_t)ix[g].y * HD + rl * 8));
            uint4 u2 = __ldg(reinterpret_cast<const uint4*>(g_embh + (size_t)ix[g].z * HD + rl * 8));
            uint4 u3 = __ldg(reinterpret_cast<const uint4*>(g_embh + (size_t)ix[g].w * HD + rl * 8));
#define ACCUM(U, W)                                                              \
            {                                                                    \
                float2 f0 = __half22float2(*reinterpret_cast<__half2*>(&U.x));  \
                float2 f1 = __half22float2(*reinterpret_cast<__half2*>(&U.y));  \
                float2 f2 = __half22float2(*reinterpret_cast<__half2*>(&U.z));  \
                float2 f3 = __half22float2(*reinterpret_cast<__half2*>(&U.w));  \
                acc[0] = fmaf(W, f0.x, acc[0]); acc[1] = fmaf(W, f0.y, acc[1]); \
                acc[2] = fmaf(W, f1.x, acc[2]); acc[3] = fmaf(W, f1.y, acc[3]); \
                acc[4] = fmaf(W, f2.x, acc[4]); acc[5] = fmaf(W, f2.y, acc[5]); \
                acc[6] = fmaf(W, f3.x, acc[6]); acc[7] = fmaf(W, f3.y, acc[7]); \
            }
            ACCUM(u0, w[g].x) ACCUM(u1, w[g].y) ACCUM(u2, w[g].z) ACCUM(u3, w[g].w)
#undef ACCUM
        }
    }
}

// ---------------- warp-specialized producer/consumer dataflow ----------------
__global__ void __launch_bounds__(256, 2)
fused_kernel(const float* __restrict__ xw, const int* __restrict__ xi,
             const int* __restrict__ tree,
             const float* __restrict__ Wz, const float* __restrict__ Uz,
             const float* __restrict__ bz,
             const float* __restrict__ Wr, const float* __restrict__ Ur,
             const float* __restrict__ br,
             const float* __restrict__ Wh, const float* __restrict__ Uh,
             const float* __restrict__ bh,
             const int* __restrict__ np_ptr, int L, int n_steps,
             float* __restrict__ out) {
    extern __shared__ float sm[];
    float* sWzr = sm;             // [k*128 + 4l + {Wz2l,Wz2l+1,Wr2l,Wr2l+1}]
    float* sWh2 = sm + 8192;
    float* sUzr = sm + 12288;
    float* sUh2 = sm + 20480;
    float* sXe = sm + 24576;      // 6 producer warps x 64
    float* sP  = sm + 24960;      // 2 consumer warps x 64
    float* sPr = sm + 25088;      // 2 consumer warps x 64

    int tid = threadIdx.x;
    int wid = tid >> 5, l = tid & 31;
    int rl = l & 7, rg = l >> 3;

    // pack weight matrices into interleaved smem layouts
    for (int t = tid; t < 8192; t += 256) {
        int k = t >> 7, q = t & 127, lane = q >> 2, c = q & 3;
        int j = 2 * lane + (c & 1);
        sWzr[t] = (c < 2 ? Wz : Wr)[j * 64 + k];
        sUzr[t] = (c < 2 ? Uz : Ur)[j * 64 + k];
    }
    for (int t = tid; t < 4096; t += 256) {
        int kp = t >> 7, q = t & 127, lane = q >> 2, c = q & 3;
        int j = 2 * lane + (c & 1);
        int k = 2 * kp + (c >> 1);
        sWh2[t] = Wh[j * 64 + k];
        sUh2[t] = Uh[j * 64 + k];
    }
    float2 bz2 = reinterpret_cast<const float2*>(bz)[l];
    float2 br2 = reinterpret_cast<const float2*>(br)[l];
    float2 bh2 = reinterpret_cast<const float2*>(bh)[l];
    int np1 = np_ptr[0] - 1;
    __syncthreads();

    float2 lm = make_float2(-3.402823466e38f, -3.402823466e38f);

    if (wid < PROD_W) {
        // ================= PRODUCER: gather + W matvecs, never waits =================
        const float4* Wzr4 = reinterpret_cast<const float4*>(sWzr);
        const float4* Wh4  = reinterpret_cast<const float4*>(sWh2);
        float* xe_w = sXe + wid * 64;
        int gp = blockIdx.x * PROD_W + wid;

        for (int i = gp; i < n_steps; i += NPROD) {
            float acc[8] = {0.f, 0.f, 0.f, 0.f, 0.f, 0.f, 0.f, 0.f};
            const float* xwr = xw + (size_t)i * L;
            const int* xir = xi + (size_t)i * L;
            for (int r0 = 0; r0 < L; r0 += GCH)
                gather_chunk(xwr, xir, r0, rl, rg, acc);
#pragma unroll
            for (int u = 0; u < 8; u++) {
                acc[u] += __shfl_xor_sync(0xffffffffu, acc[u], 8);
                acc[u] += __shfl_xor_sync(0xffffffffu, acc[u], 16);
            }
            if (rg == 0) {
#pragma unroll
                for (int u = 0; u < 8; u++) xe_w[rl * 8 + u] = acc[u];
            }
            __syncwarp();

            // W matvecs: a = W xe + b
            float4 wzrA = make_float4(bz2.x, bz2.y, br2.x, br2.y);
            float4 wzrB = make_float4(0.f, 0.f, 0.f, 0.f);
            float2 whA = bh2, whB = make_float2(0.f, 0.f);
#pragma unroll
            for (int k = 0; k < 64; k += 2) {
                float2 x = *reinterpret_cast<const float2*>(&xe_w[k]);
                float4 m0 = Wzr4[k * 32 + l];
                float4 m1 = Wzr4[(k + 1) * 32 + l];
                wzrA.x = fmaf(m0.x, x.x, wzrA.x); wzrA.y = fmaf(m0.y, x.x, wzrA.y);
                wzrA.z = fmaf(m0.z, x.x, wzrA.z); wzrA.w = fmaf(m0.w, x.x, wzrA.w);
                wzrB.x = fmaf(m1.x, x.y, wzrB.x); wzrB.y = fmaf(m1.y, x.y, wzrB.y);
                wzrB.z = fmaf(m1.z, x.y, wzrB.z); wzrB.w = fmaf(m1.w, x.y, wzrB.w);
                float4 mh = Wh4[(k >> 1) * 32 + l];
                whA.x = fmaf(mh.x, x.x, whA.x); whA.y = fmaf(mh.y, x.x, whA.y);
                whB.x = fmaf(mh.z, x.y, whB.x); whB.y = fmaf(mh.w, x.y, whB.y);
            }
            float2 az2 = make_float2(wzrA.x + wzrB.x, wzrA.y + wzrB.y);
            float2 ar2 = make_float2(wzrA.z + wzrB.z, wzrA.w + wzrB.w);
            float2 ah2 = make_float2(whA.x + whB.x, whA.y + whB.y);

            __stcg(reinterpret_cast<float2*>(g_az + (size_t)i * HD) + l, az2);
            __stcg(reinterpret_cast<float2*>(g_ar + (size_t)i * HD) + l, ar2);
            __stcg(reinterpret_cast<float2*>(g_ah + (size_t)i * HD) + l, ah2);
            __threadfence();     // release a stores
            __syncwarp();
            if (l == 0) g_aready[i] = 1;
        }
    } else {
        // ================= CONSUMER: recurrence dataflow =================
        const float4* Uzr4 = reinterpret_cast<const float4*>(sUzr);
        const float4* Uh4  = reinterpret_cast<const float4*>(sUh2);
        int cw = wid - PROD_W;
        float* p_w  = sP + cw * 64;
        float* pr_w = sPr + cw * 64;
        int gc = blockIdx.x * CONS_W + cw;

        for (int i = gc; i < n_steps; i += NCONS) {
            // dep(i): last j<i writing node tree[i,0]
            int v = tree[2 * i];
            int c = g_cnt[v];
            int d = -1;
            if (c <= SLOTS) {
                if (l < c) {
                    int j = g_buck[v * SLOTS + l];
                    if (j < i) d = j;
                }
            } else {
                if (l == 0)
                    for (int j = i - 1; j >= 0; --j)
                        if (g_wr[j] == v) { d = j; break; }
            }
            d = __reduce_max_sync(0xffffffffu, d);

            // wait for a-vectors
            if (l == 0) {
                int cnt = 0;
                while (g_aready[i] == 0)
                    if (((++cnt) & 15) == 0) __nanosleep(128);
            }
            __syncwarp();
            __threadfence();   // acquire
            float2 az2 = __ldcg(reinterpret_cast<const float2*>(g_az + (size_t)i * HD) + l);
            float2 ar2 = __ldcg(reinterpret_cast<const float2*>(g_ar + (size_t)i * HD) + l);
            float2 ah2 = __ldcg(reinterpret_cast<const float2*>(g_ah + (size_t)i * HD) + l);

            // wait for parent h
            float2 p2;
            if (d >= 0) {
                if (l == 0) {
                    int cnt = 0;
                    while (g_ready[d] == 0)
                        if (((++cnt) & 15) == 0) __nanosleep(64);
                }
                __syncwarp();
                __threadfence();   // acquire
                p2 = __ldcg(reinterpret_cast<const float2*>(g_h + (size_t)d * HD) + l);
            } else {
                p2 = make_float2(0.f, 0.f);
            }
            *reinterpret_cast<float2*>(&p_w[2 * l]) = p2;
            __syncwarp();

            // U z/r matvec
            float4 sA = make_float4(az2.x, az2.y, ar2.x, ar2.y);
            float4 sB = make_float4(0.f, 0.f, 0.f, 0.f);
#pragma unroll
            for (int k = 0; k < 64; k += 2) {
                float2 x = *reinterpret_cast<const float2*>(&p_w[k]);
                float4 m0 = Uzr4[k * 32 + l];
                float4 m1 = Uzr4[(k + 1) * 32 + l];
                sA.x = fmaf(m0.x, x.x, sA.x); sA.y = fmaf(m0.y, x.x, sA.y);
                sA.z = fmaf(m0.z, x.x, sA.z); sA.w = fmaf(m0.w, x.x, sA.w);
                sB.x = fmaf(m1.x, x.y, sB.x); sB.y = fmaf(m1.y, x.y, sB.y);
                sB.z = fmaf(m1.z, x.y, sB.z); sB.w = fmaf(m1.w, x.y, sB.w);
            }
            float2 z2, r2;
            z2.x = fminf(fmaxf(0.2f * (sA.x + sB.x) + 0.5f, 0.f), 1.f);
            z2.y = fminf(fmaxf(0.2f * (sA.y + sB.y) + 0.5f, 0.f), 1.f);
            r2.x = fminf(fmaxf(0.2f * (sA.z + sB.z) + 0.5f, 0.f), 1.f);
            r2.y = fminf(fmaxf(0.2f * (sA.w + sB.w) + 0.5f, 0.f), 1.f);
            *reinterpret_cast<float2*>(&pr_w[2 * l]) =
                make_float2(p2.x * r2.x, p2.y * r2.y);
            __syncwarp();

            // Uh matvec
            float2 hA = ah2, hB = make_float2(0.f, 0.f);
#pragma unroll
            for (int kp = 0; kp < 32; kp++) {
                float2 x = *reinterpret_cast<const float2*>(&pr_w[2 * kp]);
                float4 m = Uh4[kp * 32 + l];
                hA.x = fmaf(m.x, x.x, hA.x); hA.y = fmaf(m.y, x.x, hA.y);
                hB.x = fmaf(m.z, x.y, hB.x); hB.y = fmaf(m.w, x.y, hB.y);
            }
            float2 h2;
            h2.x = z2.x * p2.x + (1.f - z2.x) * tanhf(hA.x + hB.x);
            h2.y = z2.y * p2.y + (1.f - z2.y) * tanhf(hA.y + hB.y);

            __stcg(reinterpret_cast<float2*>(g_h + (size_t)i * HD) + l, h2);
            if (i >= np1) {
                lm.x = fmaxf(lm.x, h2.x);
                lm.y = fmaxf(lm.y, h2.y);
            }
            __threadfence();     // release h stores
            __syncwarp();
            if (l == 0) g_ready[i] = 1;
        }
    }

    // fold local max, then last block writes output
    unsigned ux = __float_as_uint(lm.x);
    ux = (ux & 0x80000000u) ? ~ux : (ux | 0x80000000u);
    unsigned uy = __float_as_uint(lm.y);
    uy = (uy & 0x80000000u) ? ~uy : (uy | 0x80000000u);
    atomicMax(&g_max[2 * l], ux);
    atomicMax(&g_max[2 * l + 1], uy);
    __threadfence();
    __syncthreads();
    __shared__ unsigned s_last;
    if (tid == 0) s_last = (atomicAdd(&g_done, 1u) == BLKS - 1) ? 1u : 0u;
    __syncthreads();
    if (s_last && tid < HD) {
        unsigned u = atomicMax(&g_max[tid], 0u);   // atomic read of final value
        unsigned b = (u & 0x80000000u) ? (u & 0x7fffffffu) : ~u;
        out[tid] = __uint_as_float(b);
    }
}

// ---------------- launch ----------------
extern "C" void kernel_launch(void* const* d_in, const int* in_sizes, int n_in,
                              void* d_out, int out_size) {
    const float* xw = (const float*)d_in[0];
    const int* xi = (const int*)d_in[1];
    const int* tree = (const int*)d_in[2];
    const int* np = (const int*)d_in[3];
    const float* emb = (const float*)d_in[4];
    const float* Wz = (const float*)d_in[5];
    const float* Uz = (const float*)d_in[6];
    const float* bz = (const float*)d_in[7];
    const float* Wr = (const float*)d_in[8];
    const float* Ur = (const float*)d_in[9];
    const float* br = (const float*)d_in[10];
    const float* Wh = (const float*)d_in[11];
    const float* Uh = (const float*)d_in[12];
    const float* bh = (const float*)d_in[13];

    int N = in_sizes[2] / 2;      // tree is [N,2]
    int L = in_sizes[0] / N;      // x_word is [N,L]
    int n_steps = N - 1;
    int emb_total = in_sizes[4];  // V*H floats

    static int smem_set = 0;
    const int SMEM_BYTES = 25216 * 4;   // 100864
    if (!smem_set) {
        cudaFuncSetAttribute(fused_kernel,
                             cudaFuncAttributeMaxDynamicSharedMemorySize, SMEM_BYTES);
        smem_set = 1;
    }

    int prep_threads = (emb_total + 7) / 8;
    if (prep_threads < MAXN) prep_threads = MAXN;
    prep_kernel<<<(prep_threads + 255) / 256, 256>>>(emb, tree, n_steps, emb_total);
    fill_kernel<<<(n_steps + 255) / 256, 256>>>(tree, n_steps);
    fused_kernel<<<BLKS, 256, SMEM_BYTES>>>(xw, xi, tree, Wz, Uz, bz, Wr, Ur, br,
                                            Wh, Uh, bh, np, L, n_steps,
                                            (float*)d_out);
}